// round 12
// baseline (speedup 1.0000x reference)
#include <cuda_runtime.h>
#include <math.h>

// Problem constants: B=4, N=16, K=16, H=64, O=1
#define ZB 4
#define NN 16
#define NK 16
#define NH 64

// Per-block partials: [a(16)][sub(32)][z*64+h(256)] = 512 KB.
// Fully overwritten every launch by plain STG -> no init, no atomics.
__device__ float    g_part[16 * 32 * 256];
// Per-a-group completion counters + work-stealing grain counters.
// Statically 0; reset by each group's finisher -> replay-invariant.
__device__ unsigned g_count[16];
__device__ unsigned g_next[16];

// ---------------------------------------------------------------------------
// Inline basis eval (fast intrinsics; tolerance 1e-3, this is ~1e-6):
// P[z,i,j,k,:] = cutoff*exp(-beta*(exp(-norm)-mean_k)^2) * diff / norm_sq
// ---------------------------------------------------------------------------
__device__ __forceinline__ float3 smear_vec(const float* __restrict__ xi,
                                            const float* __restrict__ xj,
                                            int k) {
    float d0 = xi[0] - xj[0];
    float d1 = xi[1] - xj[1];
    float d2 = xi[2] - xj[2];

    float ns = fmaf(d0, d0, fmaf(d1, d1, fmaf(d2, d2, 1e-5f)));
    float rs = __frsqrt_rn(ns);
    float norm = ns * rs;                            // sqrt(ns)

    const float start = 0.006737946999085467f;       // exp(-5)
    float mean = start + (float)k * (1.0f - start) * (1.0f / 15.0f);
    const float bden = 0.125f * (1.0f - start);
    const float beta = 1.0f / (bden * bden);

    float cutoff = (norm < 5.0f)
                 ? 0.5f * (cospif(norm * 0.2f) + 1.0f)
                 : 0.0f;
    float e = __expf(-norm);
    float dd = e - mean;
    float smear = cutoff * __expf(-beta * dd * dd);
    float so = __fdividef(smear, ns);
    return make_float3(so * d0, so * d1, so * d2);
}

// ---------------------------------------------------------------------------
// Per-a-group finisher: reduce 32 partials (32 KB, L2), silu, dot with w_fc,
// write out[z*16+a] for z=0..3, reset this group's counters.
// __noinline__ so its register demand cannot inflate the hot loop.
// ---------------------------------------------------------------------------
__device__ __noinline__ void finish_group(int a,
                                          const float* __restrict__ w_fc,
                                          const float* __restrict__ b_fc,
                                          float* __restrict__ out,
                                          float* sred) {
    int t = threadIdx.x;                       // t = z*64 + h

    __threadfence();                           // acquire side vs other blocks' STGs

    const float* p = &g_part[(a * 32) * 256 + t];
    float v = 0.0f;
#pragma unroll
    for (int sub = 0; sub < 32; sub++) v += __ldcg(p + sub * 256);

    float sg = (v / (1.0f + __expf(-v))) * w_fc[t & 63];

    // warp-reduce 32 lanes; two warps per z
#pragma unroll
    for (int o = 16; o > 0; o >>= 1) sg += __shfl_xor_sync(0xFFFFFFFFu, sg, o);
    if ((t & 31) == 0) sred[t >> 5] = sg;      // 8 partials
    __syncthreads();

    if (t < ZB) out[t * NN + a] = sred[2 * t] + sred[2 * t + 1] + b_fc[0];
    if (t == 0) { g_count[a] = 0u; g_next[a] = 0u; }   // reset for replay
}

// ---------------------------------------------------------------------------
// Single fused kernel, WARP-autonomous work stealing. 512 blocks = 16
// a-groups x 32 blocks, one wave. Each WARP independently grabs 16 KB grains
// (slice quarter) from its group's 1024-grain pool: no block barriers in the
// mainloop at all. Per-warp 1 KB smem coef table, __syncwarp only.
// ---------------------------------------------------------------------------
__global__ void __launch_bounds__(256, 4) k_fused(const float* __restrict__ W,
                                                  const float* __restrict__ x,
                                                  const float* __restrict__ w_fc,
                                                  const float* __restrict__ b_fc,
                                                  float* __restrict__ out) {
    __shared__ __align__(16) float  sx[ZB * NN * 3];   // coords, 768 B
    __shared__ __align__(16) float  sP1[1024 * 3];     // 12 KB: P1[z][b][k]*3
    __shared__ __align__(16) float4 scoefw[8][64];     // 8 KB: per-warp coef; sred later
    __shared__ unsigned s_old;

    int a = blockIdx.x >> 5;                   // 0..15 (static per block)

    int t    = threadIdx.x;
    int lane = t & 31;
    int wid  = t >> 5;                         // warp 0..7
    int h4   = t & 15;

    // --- load coords ---
    if (t < ZB * NN * 3) sx[t] = x[t];
    __syncthreads();

    // --- P1 table: P[z,a,b,k,:] for all (z,b,k) — 1024 evals, 4/thread ---
    for (int i = t; i < 1024; i += 256) {
        int z = i >> 8;
        int b = (i >> 4) & 15;
        int k = i & 15;
        float3 v = smear_vec(&sx[(z * NN + a) * 3], &sx[(z * NN + b) * 3], k);
        float* p = &sP1[i * 3];
        p[0] = v.x; p[1] = v.y; p[2] = v.z;
    }
    __syncthreads();                           // P1 ready; no more block barriers
                                               // until the epilogue

    float acc0x = 0.f, acc0y = 0.f, acc0z = 0.f, acc0w = 0.f;
    float acc1x = 0.f, acc1y = 0.f, acc1z = 0.f, acc1w = 0.f;
    float acc2x = 0.f, acc2y = 0.f, acc2z = 0.f, acc2w = 0.f;
    float acc3x = 0.f, acc3y = 0.f, acc3z = 0.f, acc3w = 0.f;

    int jp = lane >> 4;                        // j parity within warp (0/1)

    // --- warp-autonomous grain loop: 16 KB grains, pool of 1024 per group ---
    for (;;) {
        unsigned gl0 = 0;
        if (lane == 0) gl0 = atomicAdd(&g_next[a], 1u);
        unsigned gl = __shfl_sync(0xFFFFFFFFu, gl0, 0);
        if (gl >= 1024u) break;

        int slice = (int)(gl >> 2);            // 0..255  -> (b,d)
        int q     = (int)(gl & 3);             // e-quarter 0..3
        int b = slice >> 4;
        int d = slice & 15;

        const float4* Wg = (const float4*)W
                         + (((size_t)a * 256 + slice) << 12) + ((size_t)q << 10);

        // prefetch this 16 KB grain (128 lines, 4/lane) to L2
        {
            const char* pf = (const char*)Wg;
#pragma unroll
            for (int p = 0; p < 4; p++)
                asm volatile("prefetch.global.L2 [%0];"
                             :: "l"(pf + (size_t)(lane + 32 * p) * 128));
        }

        // --- per-warp coef table: 64 entries, 2 per lane ---
#pragma unroll
        for (int hh = 0; hh < 2; hh++) {
            int jl = lane + hh * 32;           // 0..63
            int e  = q * 4 + (jl >> 4);
            int k  = jl & 15;
            float cf[4];
#pragma unroll
            for (int z = 0; z < 4; z++) {
                float3 p2 = smear_vec(&sx[(z * NN + d) * 3], &sx[(z * NN + e) * 3], k);
                const float* p1 = &sP1[(((z * NN) + b) * NK + k) * 3];
                cf[z] = p1[0] * p2.x + p1[1] * p2.y + p1[2] * p2.z;
            }
            scoefw[wid][jl] = make_float4(cf[0], cf[1], cf[2], cf[3]);
        }
        __syncwarp();

        // --- stream 16 KB: 1024 float4, 32/lane, 8 batches of 4 loads ---
#pragma unroll
        for (int it = 0; it < 8; it++) {
            float4 w0 = __ldcs(Wg + (size_t)(it * 4 + 0) * 32 + lane);
            float4 w1 = __ldcs(Wg + (size_t)(it * 4 + 1) * 32 + lane);
            float4 w2 = __ldcs(Wg + (size_t)(it * 4 + 2) * 32 + lane);
            float4 w3 = __ldcs(Wg + (size_t)(it * 4 + 3) * 32 + lane);

            float4 c;
            c = scoefw[wid][(it * 4 + 0) * 2 + jp];
            acc0x += c.x * w0.x; acc0y += c.x * w0.y; acc0z += c.x * w0.z; acc0w += c.x * w0.w;
            acc1x += c.y * w0.x; acc1y += c.y * w0.y; acc1z += c.y * w0.z; acc1w += c.y * w0.w;
            acc2x += c.z * w0.x; acc2y += c.z * w0.y; acc2z += c.z * w0.z; acc2w += c.z * w0.w;
            acc3x += c.w * w0.x; acc3y += c.w * w0.y; acc3z += c.w * w0.z; acc3w += c.w * w0.w;

            c = scoefw[wid][(it * 4 + 1) * 2 + jp];
            acc0x += c.x * w1.x; acc0y += c.x * w1.y; acc0z += c.x * w1.z; acc0w += c.x * w1.w;
            acc1x += c.y * w1.x; acc1y += c.y * w1.y; acc1z += c.y * w1.z; acc1w += c.y * w1.w;
            acc2x += c.z * w1.x; acc2y += c.z * w1.y; acc2z += c.z * w1.z; acc2w += c.z * w1.w;
            acc3x += c.w * w1.x; acc3y += c.w * w1.y; acc3z += c.w * w1.z; acc3w += c.w * w1.w;

            c = scoefw[wid][(it * 4 + 2) * 2 + jp];
            acc0x += c.x * w2.x; acc0y += c.x * w2.y; acc0z += c.x * w2.z; acc0w += c.x * w2.w;
            acc1x += c.y * w2.x; acc1y += c.y * w2.y; acc1z += c.y * w2.z; acc1w += c.y * w2.w;
            acc2x += c.z * w2.x; acc2y += c.z * w2.y; acc2z += c.z * w2.z; acc2w += c.z * w2.w;
            acc3x += c.w * w2.x; acc3y += c.w * w2.y; acc3z += c.w * w2.z; acc3w += c.w * w2.w;

            c = scoefw[wid][(it * 4 + 3) * 2 + jp];
            acc0x += c.x * w3.x; acc0y += c.x * w3.y; acc0z += c.x * w3.z; acc0w += c.x * w3.w;
            acc1x += c.y * w3.x; acc1y += c.y * w3.y; acc1z += c.y * w3.z; acc1w += c.y * w3.w;
            acc2x += c.z * w3.x; acc2y += c.z * w3.y; acc2z += c.z * w3.z; acc2w += c.z * w3.w;
            acc3x += c.w * w3.x; acc3y += c.w * w3.y; acc3z += c.w * w3.z; acc3w += c.w * w3.w;
        }
        __syncwarp();                          // lanes done reading scoefw[wid]
    }

    // --- epilogue: shfl-combine jp pairs, 8-warp smem reduce, plain STG ---
#define SHFL_ADD(v) v += __shfl_xor_sync(0xFFFFFFFFu, v, 16)
    SHFL_ADD(acc0x); SHFL_ADD(acc0y); SHFL_ADD(acc0z); SHFL_ADD(acc0w);
    SHFL_ADD(acc1x); SHFL_ADD(acc1y); SHFL_ADD(acc1z); SHFL_ADD(acc1w);
    SHFL_ADD(acc2x); SHFL_ADD(acc2y); SHFL_ADD(acc2z); SHFL_ADD(acc2w);
    SHFL_ADD(acc3x); SHFL_ADD(acc3y); SHFL_ADD(acc3z); SHFL_ADD(acc3w);
#undef SHFL_ADD

    __syncthreads();                           // ALL warps done -> scoefw reusable
    if (lane < 16) {
        float4* r4 = (float4*)scoefw;          // [8 warps][4 z][16 h4] of float4
        int base = (wid * 4) * 16 + h4;
        r4[base + 0 * 16] = make_float4(acc0x, acc0y, acc0z, acc0w);
        r4[base + 1 * 16] = make_float4(acc1x, acc1y, acc1z, acc1w);
        r4[base + 2 * 16] = make_float4(acc2x, acc2y, acc2z, acc2w);
        r4[base + 3 * 16] = make_float4(acc3x, acc3y, acc3z, acc3w);
    }
    __syncthreads();

    const float* sredf = (const float*)scoefw;
    float sum = 0.0f;
#pragma unroll
    for (int w2 = 0; w2 < 8; w2++) sum += sredf[w2 * 256 + t];

    g_part[blockIdx.x * 256 + t] = sum;        // coalesced STG, no atomic

    // --- per-a-group last-block-done ---
    __threadfence();                           // my STG visible device-wide
    __syncthreads();                           // all threads' fences done
    if (t == 0) s_old = atomicAdd(&g_count[a], 1);
    __syncthreads();

    if (s_old == 31u)
        finish_group(a, w_fc, b_fc, out, (float*)scoefw);
}

// ---------------------------------------------------------------------------
extern "C" void kernel_launch(void* const* d_in, const int* in_sizes, int n_in,
                              void* d_out, int out_size) {
    const float* x   = nullptr;
    const float* W   = nullptr;
    const float* wfc = nullptr;
    const float* bfc = nullptr;
    for (int i = 0; i < n_in; i++) {
        long long s = in_sizes[i];
        if      (s == (long long)ZB * NN * 3)                 x   = (const float*)d_in[i];
        else if (s == (long long)NN * NN * NN * NN * NK * NH) W   = (const float*)d_in[i];
        else if (s == NH)                                     wfc = (const float*)d_in[i];
        else if (s == 1)                                      bfc = (const float*)d_in[i];
    }

    k_fused<<<512, 256>>>(W, x, wfc, bfc, (float*)d_out);
}

// round 13
// speedup vs baseline: 1.1235x; 1.1235x over previous
#include <cuda_runtime.h>
#include <math.h>

// Problem constants: B=4, N=16, K=16, H=64, O=1
#define ZB 4
#define NN 16
#define NK 16
#define NH 64
#define GB 37                                  // blocks per a-group (16*37=592 = 4/SM on 148 SMs)

// Per-block partials: [a(16)][idx(37)][z*64+h(256)] = 592 KB.
// Fully overwritten every launch by plain STG -> no init, no atomics.
__device__ float    g_part[16 * GB * 256];
// Per-a-group completion counters + work-stealing grain counters.
// Statically 0; reset by each group's finisher -> replay-invariant.
__device__ unsigned g_count[16];
__device__ unsigned g_next[16];

// ---------------------------------------------------------------------------
// Inline basis eval (fast intrinsics; tolerance 1e-3, this is ~1e-6):
// P[z,i,j,k,:] = cutoff*exp(-beta*(exp(-norm)-mean_k)^2) * diff / norm_sq
// ---------------------------------------------------------------------------
__device__ __forceinline__ float3 smear_vec(const float* __restrict__ xi,
                                            const float* __restrict__ xj,
                                            int k) {
    float d0 = xi[0] - xj[0];
    float d1 = xi[1] - xj[1];
    float d2 = xi[2] - xj[2];

    float ns = fmaf(d0, d0, fmaf(d1, d1, fmaf(d2, d2, 1e-5f)));
    float rs = __frsqrt_rn(ns);
    float norm = ns * rs;                            // sqrt(ns)

    const float start = 0.006737946999085467f;       // exp(-5)
    float mean = start + (float)k * (1.0f - start) * (1.0f / 15.0f);
    const float bden = 0.125f * (1.0f - start);
    const float beta = 1.0f / (bden * bden);

    float cutoff = (norm < 5.0f)
                 ? 0.5f * (cospif(norm * 0.2f) + 1.0f)
                 : 0.0f;
    float e = __expf(-norm);
    float dd = e - mean;
    float smear = cutoff * __expf(-beta * dd * dd);
    float so = __fdividef(smear, ns);
    return make_float3(so * d0, so * d1, so * d2);
}

// ---------------------------------------------------------------------------
// Per-a-group finisher: reduce GB partials (37 KB, L2), silu, dot with w_fc,
// write out[z*16+a] for z=0..3, reset this group's counters.
// __noinline__ so its register demand cannot inflate the hot loop.
// ---------------------------------------------------------------------------
__device__ __noinline__ void finish_group(int a,
                                          const float* __restrict__ w_fc,
                                          const float* __restrict__ b_fc,
                                          float* __restrict__ out,
                                          float* sred) {
    int t = threadIdx.x;                       // t = z*64 + h

    __threadfence();                           // acquire side vs other blocks' STGs

    const float* p = &g_part[(a * GB) * 256 + t];
    float v = 0.0f;
#pragma unroll
    for (int sub = 0; sub < GB; sub++) v += __ldcg(p + sub * 256);

    float sg = (v / (1.0f + __expf(-v))) * w_fc[t & 63];

    // warp-reduce 32 lanes; two warps per z
#pragma unroll
    for (int o = 16; o > 0; o >>= 1) sg += __shfl_xor_sync(0xFFFFFFFFu, sg, o);
    if ((t & 31) == 0) sred[t >> 5] = sg;      // 8 partials
    __syncthreads();

    if (t < ZB) out[t * NN + a] = sred[2 * t] + sred[2 * t + 1] + b_fc[0];
    if (t == 0) { g_count[a] = 0u; g_next[a] = 0u; }   // reset for replay
}

// ---------------------------------------------------------------------------
// Single fused kernel, block-level work stealing, FULL grid. 592 blocks =
// 16 a-groups x 37 blocks -> exactly 4 blocks on every SM (max warps).
// Each group's 37 blocks dynamically grab 64 KB grains (b,d) from a
// 256-grain pool. P1[z,b,k] table hoisted to smem; per-grain coef = 4 P2
// evals/thread. Last block of each group finishes that group's outputs.
// ---------------------------------------------------------------------------
__global__ void __launch_bounds__(256, 4) k_fused(const float* __restrict__ W,
                                                  const float* __restrict__ x,
                                                  const float* __restrict__ w_fc,
                                                  const float* __restrict__ b_fc,
                                                  float* __restrict__ out) {
    __shared__ __align__(16) float  sx[ZB * NN * 3];   // coords, 768 B
    __shared__ __align__(16) float  sP1[1024 * 3];     // 12 KB: P1[z][b][k]*3; sred later
    __shared__ float4 scoef[256];                      // 4 KB coef table
    __shared__ int      s_gl;
    __shared__ unsigned s_old;

    int a = blockIdx.x / GB;                   // 0..15 (static per block)

    int t  = threadIdx.x;
    int h4 = t & 15;                           // float4 index within 64 h
    int g  = t >> 4;                           // j-row group 0..15

    // --- load coords ---
    if (t < ZB * NN * 3) sx[t] = x[t];
    __syncthreads();

    // --- P1 table: P[z,a,b,k,:] for all (z,b,k) — 1024 evals, 4/thread ---
    for (int i = t; i < 1024; i += 256) {
        int z = i >> 8;
        int b = (i >> 4) & 15;
        int k = i & 15;
        float3 v = smear_vec(&sx[(z * NN + a) * 3], &sx[(z * NN + b) * 3], k);
        float* p = &sP1[i * 3];
        p[0] = v.x; p[1] = v.y; p[2] = v.z;
    }
    // (no sync here: the first grab-sync below orders P1 writes vs reads)

    float acc0x = 0.f, acc0y = 0.f, acc0z = 0.f, acc0w = 0.f;
    float acc1x = 0.f, acc1y = 0.f, acc1z = 0.f, acc1w = 0.f;
    float acc2x = 0.f, acc2y = 0.f, acc2z = 0.f, acc2w = 0.f;
    float acc3x = 0.f, acc3y = 0.f, acc3z = 0.f, acc3w = 0.f;

    // --- work-stealing loop over 64 KB grains (pool of 256 per group) ---
    for (;;) {
        if (t == 0) s_gl = (int)atomicAdd(&g_next[a], 1u);
        __syncthreads();                       // broadcast grain; also orders
                                               // prev stream reads vs coef rewrite
        int gl = s_gl;
        if (gl >= 256) break;                  // uniform across block

        int b = gl >> 4;
        int d = gl & 15;

        const float4* Wp = (const float4*)W + (((size_t)a * 256 + gl) << 12);

        // prefetch this grain (64 KB = 512 lines) to L2 while coef builds
        {
            const char* pf = (const char*)Wp;
            asm volatile("prefetch.global.L2 [%0];" :: "l"(pf + (size_t)t * 128));
            asm volatile("prefetch.global.L2 [%0];" :: "l"(pf + (size_t)(t + 256) * 128));
        }

        // --- coef[t=(e,k)]: dot(P1[z,b,k], P2[z,d,e,k]) for z=0..3 ---
        {
            int e = t >> 4;
            int k = t & 15;
            float cf[4];
#pragma unroll
            for (int z = 0; z < 4; z++) {
                float3 p2 = smear_vec(&sx[(z * NN + d) * 3], &sx[(z * NN + e) * 3], k);
                const float* p1 = &sP1[(((z * NN) + b) * NK + k) * 3];
                cf[z] = p1[0] * p2.x + p1[1] * p2.y + p1[2] * p2.z;
            }
            scoef[t] = make_float4(cf[0], cf[1], cf[2], cf[3]);
        }
        __syncthreads();                       // coef ready for all warps

        // --- stream this 64 KB grain, loads batched 4 deep ---
        const float4* Wq = Wp + (g * 16 + h4);

#pragma unroll
        for (int it = 0; it < 16; it += 4) {
            float4 w0 = __ldcs(Wq + (size_t)(it + 0) * 256);
            float4 w1 = __ldcs(Wq + (size_t)(it + 1) * 256);
            float4 w2 = __ldcs(Wq + (size_t)(it + 2) * 256);
            float4 w3 = __ldcs(Wq + (size_t)(it + 3) * 256);

            float4 c;
            c = scoef[g + (it + 0) * 16];
            acc0x += c.x * w0.x; acc0y += c.x * w0.y; acc0z += c.x * w0.z; acc0w += c.x * w0.w;
            acc1x += c.y * w0.x; acc1y += c.y * w0.y; acc1z += c.y * w0.z; acc1w += c.y * w0.w;
            acc2x += c.z * w0.x; acc2y += c.z * w0.y; acc2z += c.z * w0.z; acc2w += c.z * w0.w;
            acc3x += c.w * w0.x; acc3y += c.w * w0.y; acc3z += c.w * w0.z; acc3w += c.w * w0.w;

            c = scoef[g + (it + 1) * 16];
            acc0x += c.x * w1.x; acc0y += c.x * w1.y; acc0z += c.x * w1.z; acc0w += c.x * w1.w;
            acc1x += c.y * w1.x; acc1y += c.y * w1.y; acc1z += c.y * w1.z; acc1w += c.y * w1.w;
            acc2x += c.z * w1.x; acc2y += c.z * w1.y; acc2z += c.z * w1.z; acc2w += c.z * w1.w;
            acc3x += c.w * w1.x; acc3y += c.w * w1.y; acc3z += c.w * w1.z; acc3w += c.w * w1.w;

            c = scoef[g + (it + 2) * 16];
            acc0x += c.x * w2.x; acc0y += c.x * w2.y; acc0z += c.x * w2.z; acc0w += c.x * w2.w;
            acc1x += c.y * w2.x; acc1y += c.y * w2.y; acc1z += c.y * w2.z; acc1w += c.y * w2.w;
            acc2x += c.z * w2.x; acc2y += c.z * w2.y; acc2z += c.z * w2.z; acc2w += c.z * w2.w;
            acc3x += c.w * w2.x; acc3y += c.w * w2.y; acc3z += c.w * w2.z; acc3w += c.w * w2.w;

            c = scoef[g + (it + 3) * 16];
            acc0x += c.x * w3.x; acc0y += c.x * w3.y; acc0z += c.x * w3.z; acc0w += c.x * w3.w;
            acc1x += c.y * w3.x; acc1y += c.y * w3.y; acc1z += c.y * w3.z; acc1w += c.y * w3.w;
            acc2x += c.z * w3.x; acc2y += c.z * w3.y; acc2z += c.z * w3.z; acc2w += c.z * w3.w;
            acc3x += c.w * w3.x; acc3y += c.w * w3.y; acc3z += c.w * w3.z; acc3w += c.w * w3.w;
        }
    }

    // --- epilogue: shfl-combine g pairs, 8-warp smem reduce, plain STG ---
#define SHFL_ADD(v) v += __shfl_xor_sync(0xFFFFFFFFu, v, 16)
    SHFL_ADD(acc0x); SHFL_ADD(acc0y); SHFL_ADD(acc0z); SHFL_ADD(acc0w);
    SHFL_ADD(acc1x); SHFL_ADD(acc1y); SHFL_ADD(acc1z); SHFL_ADD(acc1w);
    SHFL_ADD(acc2x); SHFL_ADD(acc2y); SHFL_ADD(acc2z); SHFL_ADD(acc2w);
    SHFL_ADD(acc3x); SHFL_ADD(acc3y); SHFL_ADD(acc3z); SHFL_ADD(acc3w);
#undef SHFL_ADD

    // Reuse sP1 as sred: a sync below separates its final reads from writes.
    __syncthreads();
    int lane = t & 31;
    int wrp  = t >> 5;                         // 0..7
    if (lane < 16) {
        float4* r4 = (float4*)sP1;             // [8 warps][4 z][16 h4] of float4
        int base = (wrp * 4) * 16 + h4;
        r4[base + 0 * 16] = make_float4(acc0x, acc0y, acc0z, acc0w);
        r4[base + 1 * 16] = make_float4(acc1x, acc1y, acc1z, acc1w);
        r4[base + 2 * 16] = make_float4(acc2x, acc2y, acc2z, acc2w);
        r4[base + 3 * 16] = make_float4(acc3x, acc3y, acc3z, acc3w);
    }
    __syncthreads();

    float sum = 0.0f;
#pragma unroll
    for (int w2 = 0; w2 < 8; w2++) sum += sP1[w2 * 256 + t];

    g_part[blockIdx.x * 256 + t] = sum;        // coalesced STG, no atomic

    // --- per-a-group last-block-done ---
    __threadfence();                           // my STG visible device-wide
    __syncthreads();                           // all threads' fences done
    if (t == 0) s_old = atomicAdd(&g_count[a], 1);
    __syncthreads();

    if (s_old == (unsigned)(GB - 1))
        finish_group(a, w_fc, b_fc, out, sP1);
}

// ---------------------------------------------------------------------------
extern "C" void kernel_launch(void* const* d_in, const int* in_sizes, int n_in,
                              void* d_out, int out_size) {
    const float* x   = nullptr;
    const float* W   = nullptr;
    const float* wfc = nullptr;
    const float* bfc = nullptr;
    for (int i = 0; i < n_in; i++) {
        long long s = in_sizes[i];
        if      (s == (long long)ZB * NN * 3)                 x   = (const float*)d_in[i];
        else if (s == (long long)NN * NN * NN * NN * NK * NH) W   = (const float*)d_in[i];
        else if (s == NH)                                     wfc = (const float*)d_in[i];
        else if (s == 1)                                      bfc = (const float*)d_in[i];
    }

    k_fused<<<16 * GB, 256>>>(W, x, wfc, bfc, (float*)d_out);
}

// round 14
// speedup vs baseline: 1.1903x; 1.0595x over previous
#include <cuda_runtime.h>
#include <math.h>

// Problem constants: B=4, N=16, K=16, H=64, O=1
#define ZB 4
#define NN 16
#define NK 16
#define NH 64
#define GB 37                                  // blocks per a-group (16*37=592 = 4/SM on 148 SMs)

// Per-block partials: [a(16)][idx(37)][z*64+h(256)] = 592 KB.
// Fully overwritten every launch by plain STG -> no init, no atomics.
__device__ float    g_part[16 * GB * 256];
// Per-a-group completion counters + work-stealing grain counters.
// Statically 0; reset by each group's finisher -> replay-invariant.
__device__ unsigned g_count[16];
__device__ unsigned g_next[16];

// Basis constants
#define SM_START 0.006737946999085467f                 // exp(-5)
#define SM_BETA  (1.0f / ((0.125f * (1.0f - SM_START)) * (0.125f * (1.0f - SM_START))))

// ---------------------------------------------------------------------------
// Per-a-group finisher: reduce GB partials (37 KB, L2), silu, dot with w_fc,
// write out[z*16+a] for z=0..3, reset this group's counters.
// __noinline__ so its register demand cannot inflate the hot loop.
// ---------------------------------------------------------------------------
__device__ __noinline__ void finish_group(int a,
                                          const float* __restrict__ w_fc,
                                          const float* __restrict__ b_fc,
                                          float* __restrict__ out,
                                          float* sred) {
    int t = threadIdx.x;                       // t = z*64 + h

    __threadfence();                           // acquire side vs other blocks' STGs

    const float* p = &g_part[(a * GB) * 256 + t];
    float v = 0.0f;
#pragma unroll
    for (int sub = 0; sub < GB; sub++) v += __ldcg(p + sub * 256);

    float sg = (v / (1.0f + __expf(-v))) * w_fc[t & 63];

    // warp-reduce 32 lanes; two warps per z
#pragma unroll
    for (int o = 16; o > 0; o >>= 1) sg += __shfl_xor_sync(0xFFFFFFFFu, sg, o);
    if ((t & 31) == 0) sred[t >> 5] = sg;      // 8 partials
    __syncthreads();

    if (t < ZB) out[t * NN + a] = sred[2 * t] + sred[2 * t + 1] + b_fc[0];
    if (t == 0) { g_count[a] = 0u; g_next[a] = 0u; }   // reset for replay
}

// ---------------------------------------------------------------------------
// Single fused kernel, block-level work stealing, full 592-block grid.
// NEW in this round: the basis eval is factored as
//   P[z,i,j,k,c] = D(z,i,j,c) * exp(-beta*(E(z,i,j)-mean_k)^2),
//   D = cutoff*diff/ns, E = exp(-norm)   (both k-independent).
// A 16 KB smem table sDE[z,i,j]=(D0,D1,D2,E) is built ONCE per block; the
// per-grain coef build is then just 2 broadcast LDS.128 + 2 __expf + dot.
// ---------------------------------------------------------------------------
__global__ void __launch_bounds__(256, 4) k_fused(const float* __restrict__ W,
                                                  const float* __restrict__ x,
                                                  const float* __restrict__ w_fc,
                                                  const float* __restrict__ b_fc,
                                                  float* __restrict__ out) {
    __shared__ __align__(16) float  sx[ZB * NN * 3];   // coords, 768 B
    __shared__ __align__(16) float4 sDE[1024];         // 16 KB: (D,E)[z][i][j]; sred later
    __shared__ float4 scoef[256];                      // 4 KB coef table
    __shared__ int      s_gl;
    __shared__ unsigned s_old;

    int a = blockIdx.x / GB;                   // 0..15 (static per block)

    int t  = threadIdx.x;
    int h4 = t & 15;                           // float4 index within 64 h
    int g  = t >> 4;                           // j-row group 0..15

    // --- load coords ---
    if (t < ZB * NN * 3) sx[t] = x[t];
    __syncthreads();

    // --- (D,E) table: 1024 entries (z,i,j), 4 per thread ---
    for (int i = t; i < 1024; i += 256) {
        int z  = i >> 8;
        int r  = (i >> 4) & 15;                // i-index
        int cj = i & 15;                       // j-index
        const float* xi = &sx[(z * NN + r) * 3];
        const float* xj = &sx[(z * NN + cj) * 3];
        float d0 = xi[0] - xj[0];
        float d1 = xi[1] - xj[1];
        float d2 = xi[2] - xj[2];
        float ns = fmaf(d0, d0, fmaf(d1, d1, fmaf(d2, d2, 1e-5f)));
        float rs = __frsqrt_rn(ns);
        float norm = ns * rs;
        float cutoff = (norm < 5.0f)
                     ? 0.5f * (cospif(norm * 0.2f) + 1.0f)
                     : 0.0f;
        float E  = __expf(-norm);
        float so = __fdividef(cutoff, ns);
        sDE[i] = make_float4(so * d0, so * d1, so * d2, E);
    }
    // (no sync here: the first grab-sync below orders table writes vs reads)

    // per-thread k is fixed -> hoist mean_k
    float mean_k = SM_START + (float)(t & 15) * (1.0f - SM_START) * (1.0f / 15.0f);
    int   e_     = t >> 4;                     // e-index for coef builds

    float acc0x = 0.f, acc0y = 0.f, acc0z = 0.f, acc0w = 0.f;
    float acc1x = 0.f, acc1y = 0.f, acc1z = 0.f, acc1w = 0.f;
    float acc2x = 0.f, acc2y = 0.f, acc2z = 0.f, acc2w = 0.f;
    float acc3x = 0.f, acc3y = 0.f, acc3z = 0.f, acc3w = 0.f;

    // --- work-stealing loop over 64 KB grains (pool of 256 per group) ---
    for (;;) {
        if (t == 0) s_gl = (int)atomicAdd(&g_next[a], 1u);
        __syncthreads();                       // broadcast grain; also orders
                                               // prev stream reads vs coef rewrite
        int gl = s_gl;
        if (gl >= 256) break;                  // uniform across block

        int b = gl >> 4;
        int d = gl & 15;

        const float4* Wp = (const float4*)W + (((size_t)a * 256 + gl) << 12);

        // prefetch this grain (64 KB = 512 lines) to L2 while coef builds
        {
            const char* pf = (const char*)Wp;
            asm volatile("prefetch.global.L2 [%0];" :: "l"(pf + (size_t)t * 128));
            asm volatile("prefetch.global.L2 [%0];" :: "l"(pf + (size_t)(t + 256) * 128));
        }

        // --- coef[t=(e,k)] = P1(z,a,b,k) . P2(z,d,e,k), cheap form ---
        {
            float cf[4];
#pragma unroll
            for (int z = 0; z < 4; z++) {
                float4 A1 = sDE[z * 256 + a * 16 + b];    // broadcast
                float4 A2 = sDE[z * 256 + d * 16 + e_];   // 2 addrs per warp
                float t1 = A1.w - mean_k;
                float t2 = A2.w - mean_k;
                float g1 = __expf(-SM_BETA * t1 * t1);
                float g2 = __expf(-SM_BETA * t2 * t2);
                float dot = A1.x * A2.x + A1.y * A2.y + A1.z * A2.z;
                cf[z] = dot * g1 * g2;
            }
            scoef[t] = make_float4(cf[0], cf[1], cf[2], cf[3]);
        }
        __syncthreads();                       // coef ready for all warps

        // --- stream this 64 KB grain, loads batched 4 deep ---
        const float4* Wq = Wp + (g * 16 + h4);

#pragma unroll
        for (int it = 0; it < 16; it += 4) {
            float4 w0 = __ldcs(Wq + (size_t)(it + 0) * 256);
            float4 w1 = __ldcs(Wq + (size_t)(it + 1) * 256);
            float4 w2 = __ldcs(Wq + (size_t)(it + 2) * 256);
            float4 w3 = __ldcs(Wq + (size_t)(it + 3) * 256);

            float4 c;
            c = scoef[g + (it + 0) * 16];
            acc0x += c.x * w0.x; acc0y += c.x * w0.y; acc0z += c.x * w0.z; acc0w += c.x * w0.w;
            acc1x += c.y * w0.x; acc1y += c.y * w0.y; acc1z += c.y * w0.z; acc1w += c.y * w0.w;
            acc2x += c.z * w0.x; acc2y += c.z * w0.y; acc2z += c.z * w0.z; acc2w += c.z * w0.w;
            acc3x += c.w * w0.x; acc3y += c.w * w0.y; acc3z += c.w * w0.z; acc3w += c.w * w0.w;

            c = scoef[g + (it + 1) * 16];
            acc0x += c.x * w1.x; acc0y += c.x * w1.y; acc0z += c.x * w1.z; acc0w += c.x * w1.w;
            acc1x += c.y * w1.x; acc1y += c.y * w1.y; acc1z += c.y * w1.z; acc1w += c.y * w1.w;
            acc2x += c.z * w1.x; acc2y += c.z * w1.y; acc2z += c.z * w1.z; acc2w += c.z * w1.w;
            acc3x += c.w * w1.x; acc3y += c.w * w1.y; acc3z += c.w * w1.z; acc3w += c.w * w1.w;

            c = scoef[g + (it + 2) * 16];
            acc0x += c.x * w2.x; acc0y += c.x * w2.y; acc0z += c.x * w2.z; acc0w += c.x * w2.w;
            acc1x += c.y * w2.x; acc1y += c.y * w2.y; acc1z += c.y * w2.z; acc1w += c.y * w2.w;
            acc2x += c.z * w2.x; acc2y += c.z * w2.y; acc2z += c.z * w2.z; acc2w += c.z * w2.w;
            acc3x += c.w * w2.x; acc3y += c.w * w2.y; acc3z += c.w * w2.z; acc3w += c.w * w2.w;

            c = scoef[g + (it + 3) * 16];
            acc0x += c.x * w3.x; acc0y += c.x * w3.y; acc0z += c.x * w3.z; acc0w += c.x * w3.w;
            acc1x += c.y * w3.x; acc1y += c.y * w3.y; acc1z += c.y * w3.z; acc1w += c.y * w3.w;
            acc2x += c.z * w3.x; acc2y += c.z * w3.y; acc2z += c.z * w3.z; acc2w += c.z * w3.w;
            acc3x += c.w * w3.x; acc3y += c.w * w3.y; acc3z += c.w * w3.z; acc3w += c.w * w3.w;
        }
    }

    // --- epilogue: shfl-combine g pairs, 8-warp smem reduce, plain STG ---
#define SHFL_ADD(v) v += __shfl_xor_sync(0xFFFFFFFFu, v, 16)
    SHFL_ADD(acc0x); SHFL_ADD(acc0y); SHFL_ADD(acc0z); SHFL_ADD(acc0w);
    SHFL_ADD(acc1x); SHFL_ADD(acc1y); SHFL_ADD(acc1z); SHFL_ADD(acc1w);
    SHFL_ADD(acc2x); SHFL_ADD(acc2y); SHFL_ADD(acc2z); SHFL_ADD(acc2w);
    SHFL_ADD(acc3x); SHFL_ADD(acc3y); SHFL_ADD(acc3z); SHFL_ADD(acc3w);
#undef SHFL_ADD

    // Reuse sDE as sred (16 KB >= 8 KB); sync separates final reads/writes.
    __syncthreads();
    float* sred = (float*)sDE;
    int lane = t & 31;
    int wrp  = t >> 5;                         // 0..7
    if (lane < 16) {
        float4* r4 = (float4*)sred;            // [8 warps][4 z][16 h4] of float4
        int base = (wrp * 4) * 16 + h4;
        r4[base + 0 * 16] = make_float4(acc0x, acc0y, acc0z, acc0w);
        r4[base + 1 * 16] = make_float4(acc1x, acc1y, acc1z, acc1w);
        r4[base + 2 * 16] = make_float4(acc2x, acc2y, acc2z, acc2w);
        r4[base + 3 * 16] = make_float4(acc3x, acc3y, acc3z, acc3w);
    }
    __syncthreads();

    float sum = 0.0f;
#pragma unroll
    for (int w2 = 0; w2 < 8; w2++) sum += sred[w2 * 256 + t];

    g_part[blockIdx.x * 256 + t] = sum;        // coalesced STG, no atomic

    // --- per-a-group last-block-done ---
    __threadfence();                           // my STG visible device-wide
    __syncthreads();                           // all threads' fences done
    if (t == 0) s_old = atomicAdd(&g_count[a], 1);
    __syncthreads();

    if (s_old == (unsigned)(GB - 1))
        finish_group(a, w_fc, b_fc, out, sred);
}

// ---------------------------------------------------------------------------
extern "C" void kernel_launch(void* const* d_in, const int* in_sizes, int n_in,
                              void* d_out, int out_size) {
    const float* x   = nullptr;
    const float* W   = nullptr;
    const float* wfc = nullptr;
    const float* bfc = nullptr;
    for (int i = 0; i < n_in; i++) {
        long long s = in_sizes[i];
        if      (s == (long long)ZB * NN * 3)                 x   = (const float*)d_in[i];
        else if (s == (long long)NN * NN * NN * NN * NK * NH) W   = (const float*)d_in[i];
        else if (s == NH)                                     wfc = (const float*)d_in[i];
        else if (s == 1)                                      bfc = (const float*)d_in[i];
    }

    k_fused<<<16 * GB, 256>>>(W, x, wfc, bfc, (float*)d_out);
}